// round 2
// baseline (speedup 1.0000x reference)
#include <cuda_runtime.h>

#define B_ROWS 32768
#define K_DIM  512
#define N_DIM  2048
#define VBS    256
#define NVB    128   // B_ROWS / VBS

// Scratch: GEMM output + folded BN affine (scale/shift per (virtual batch, col))
__device__ float g_Y[(size_t)B_ROWS * N_DIM];
__device__ float g_scale[NVB * N_DIM];
__device__ float g_shift[NVB * N_DIM];

// ---------------------------------------------------------------------------
// Kernel 1: fp32 GEMM  Y[m,n] = sum_k A[m,k] * W[n,k]
// A: [32768,512] row-major, W: [2048,512] row-major (both K-contiguous).
// Tiles 128x128x16, 256 threads, 8x8 per-thread micro-tile.
// ---------------------------------------------------------------------------
#define BM 128
#define BN 128
#define BK 16

__global__ __launch_bounds__(256)
void gemm_f32(const float* __restrict__ A, const float* __restrict__ W) {
    __shared__ float As[BK][BM];
    __shared__ float Bs[BK][BN];

    const int bm  = blockIdx.y * BM;
    const int bn  = blockIdx.x * BN;
    const int tid = threadIdx.x;
    const int tx  = tid & 15;
    const int ty  = tid >> 4;

    float acc[8][8];
    #pragma unroll
    for (int i = 0; i < 8; i++)
        #pragma unroll
        for (int j = 0; j < 8; j++) acc[i][j] = 0.f;

    for (int k0 = 0; k0 < K_DIM; k0 += BK) {
        // Load 128x16 tiles of A and W, stored transposed [BK][BM] in smem.
        #pragma unroll
        for (int l = 0; l < 2; l++) {
            int lin = tid + l * 256;       // 0..511 (float4 units)
            int row = lin >> 2;            // 0..127
            int kc  = (lin & 3) << 2;      // 0,4,8,12
            float4 va = *(const float4*)(A + (size_t)(bm + row) * K_DIM + k0 + kc);
            As[kc + 0][row] = va.x;
            As[kc + 1][row] = va.y;
            As[kc + 2][row] = va.z;
            As[kc + 3][row] = va.w;
            float4 vb = *(const float4*)(W + (size_t)(bn + row) * K_DIM + k0 + kc);
            Bs[kc + 0][row] = vb.x;
            Bs[kc + 1][row] = vb.y;
            Bs[kc + 2][row] = vb.z;
            Bs[kc + 3][row] = vb.w;
        }
        __syncthreads();

        #pragma unroll
        for (int kk = 0; kk < BK; kk++) {
            float a[8], b[8];
            *(float4*)(a)     = *(const float4*)(&As[kk][ty * 8]);
            *(float4*)(a + 4) = *(const float4*)(&As[kk][ty * 8 + 4]);
            *(float4*)(b)     = *(const float4*)(&Bs[kk][tx * 8]);
            *(float4*)(b + 4) = *(const float4*)(&Bs[kk][tx * 8 + 4]);
            #pragma unroll
            for (int i = 0; i < 8; i++)
                #pragma unroll
                for (int j = 0; j < 8; j++)
                    acc[i][j] = fmaf(a[i], b[j], acc[i][j]);
        }
        __syncthreads();
    }

    #pragma unroll
    for (int i = 0; i < 8; i++) {
        float* yp = g_Y + (size_t)(bm + ty * 8 + i) * N_DIM + bn + tx * 8;
        *(float4*)(yp)     = make_float4(acc[i][0], acc[i][1], acc[i][2], acc[i][3]);
        *(float4*)(yp + 4) = make_float4(acc[i][4], acc[i][5], acc[i][6], acc[i][7]);
    }
}

// ---------------------------------------------------------------------------
// Kernel 2: GhostBatchNorm statistics per (virtual batch, column).
// Folds gamma/beta: out = y*scale + shift with
//   scale = gamma * rsqrt(var + eps), shift = beta - mean*scale
// ---------------------------------------------------------------------------
__global__ __launch_bounds__(256)
void bn_stats(const float* __restrict__ gamma, const float* __restrict__ beta) {
    const int d  = blockIdx.x * 256 + threadIdx.x;  // column
    const int vb = blockIdx.y;                      // virtual batch
    const float* p = g_Y + (size_t)vb * VBS * N_DIM + d;

    float s = 0.f, s2 = 0.f;
    #pragma unroll 8
    for (int r = 0; r < VBS; r++) {
        float v = p[(size_t)r * N_DIM];
        s  += v;
        s2  = fmaf(v, v, s2);
    }
    float mean = s * (1.f / VBS);
    float var  = s2 * (1.f / VBS) - mean * mean;   // biased var, matches BN training
    float sc   = gamma[d] * rsqrtf(var + 1e-5f);
    g_scale[vb * N_DIM + d] = sc;
    g_shift[vb * N_DIM + d] = fmaf(-mean, sc, beta[d]);
}

// ---------------------------------------------------------------------------
// Kernel 3: fused normalize + prior scaling + exact sparsemax per row.
// One CTA per row (2048 cols), 8 cols/thread held in registers.
// Sparsemax threshold via Michelot's algorithm (exact finite convergence):
//   support = all; repeat: tau = (sum_{z>tau} z - 1)/|{z>tau}| until stable.
// ---------------------------------------------------------------------------
__global__ __launch_bounds__(256)
void sparsemax_fused(const float* __restrict__ priors, float* __restrict__ out) {
    const int row = blockIdx.x;
    const int vb  = row >> 8;          // row / VBS
    const int t   = threadIdx.x;
    const int c0  = t * 8;

    __shared__ float warp_s[8];
    __shared__ float warp_c[8];
    __shared__ float bcast[2];

    const float* yrow = g_Y    + (size_t)row * N_DIM;
    const float* prow = priors + (size_t)row * N_DIM;
    const float* scr  = g_scale + (size_t)vb * N_DIM;
    const float* shr  = g_shift + (size_t)vb * N_DIM;

    float z[8];
    #pragma unroll
    for (int v = 0; v < 2; v++) {
        float4 y  = *(const float4*)(yrow + c0 + v * 4);
        float4 p  = *(const float4*)(prow + c0 + v * 4);
        float4 sc = *(const float4*)(scr  + c0 + v * 4);
        float4 sh = *(const float4*)(shr  + c0 + v * 4);
        z[v * 4 + 0] = fmaf(y.x, sc.x, sh.x) * p.x;
        z[v * 4 + 1] = fmaf(y.y, sc.y, sh.y) * p.y;
        z[v * 4 + 2] = fmaf(y.z, sc.z, sh.z) * p.z;
        z[v * 4 + 3] = fmaf(y.w, sc.w, sh.w) * p.w;
    }

    // --- block reduction helper (sum + count), inlined twice below ---
    // initial tau: support = everything
    float ls = 0.f, lc = 0.f;
    #pragma unroll
    for (int i = 0; i < 8; i++) ls += z[i];
    // reduce ls (count unused on first pass)
    #pragma unroll
    for (int o = 16; o; o >>= 1) ls += __shfl_down_sync(0xffffffffu, ls, o);
    if ((t & 31) == 0) warp_s[t >> 5] = ls;
    __syncthreads();
    if (t < 32) {
        float s = (t < 8) ? warp_s[t] : 0.f;
        #pragma unroll
        for (int o = 4; o; o >>= 1) s += __shfl_down_sync(0xffffffffu, s, o);
        if (t == 0) bcast[0] = s;
    }
    __syncthreads();
    float tau   = (bcast[0] - 1.f) * (1.f / (float)N_DIM);
    float kprev = (float)N_DIM;
    __syncthreads();

    for (int it = 0; it < 64; it++) {
        ls = 0.f; lc = 0.f;
        #pragma unroll
        for (int i = 0; i < 8; i++) {
            if (z[i] > tau) { ls += z[i]; lc += 1.f; }
        }
        #pragma unroll
        for (int o = 16; o; o >>= 1) {
            ls += __shfl_down_sync(0xffffffffu, ls, o);
            lc += __shfl_down_sync(0xffffffffu, lc, o);
        }
        if ((t & 31) == 0) { warp_s[t >> 5] = ls; warp_c[t >> 5] = lc; }
        __syncthreads();
        if (t < 32) {
            float s = (t < 8) ? warp_s[t] : 0.f;
            float c = (t < 8) ? warp_c[t] : 0.f;
            #pragma unroll
            for (int o = 4; o; o >>= 1) {
                s += __shfl_down_sync(0xffffffffu, s, o);
                c += __shfl_down_sync(0xffffffffu, c, o);
            }
            if (t == 0) { bcast[0] = s; bcast[1] = c; }
        }
        __syncthreads();
        float S = bcast[0];
        float C = bcast[1];
        __syncthreads();
        if (C == kprev) break;          // support stable -> tau is exact
        tau   = (S - 1.f) / C;
        kprev = C;
    }

    float o0[8];
    #pragma unroll
    for (int i = 0; i < 8; i++) o0[i] = fmaxf(z[i] - tau, 0.f);
    float* orow = out + (size_t)row * N_DIM + c0;
    *(float4*)(orow)     = make_float4(o0[0], o0[1], o0[2], o0[3]);
    *(float4*)(orow + 4) = make_float4(o0[4], o0[5], o0[6], o0[7]);
}

// ---------------------------------------------------------------------------
extern "C" void kernel_launch(void* const* d_in, const int* in_sizes, int n_in,
                              void* d_out, int out_size) {
    const float* priors = (const float*)d_in[0];   // [32768, 2048]
    const float* feat   = (const float*)d_in[1];   // [32768, 512]
    const float* W      = (const float*)d_in[2];   // [2048, 512]
    const float* gamma  = (const float*)d_in[3];   // [2048]
    const float* beta   = (const float*)d_in[4];   // [2048]
    float* out = (float*)d_out;                    // [32768, 2048]

    dim3 ggrid(N_DIM / BN, B_ROWS / BM);           // (16, 256)
    gemm_f32<<<ggrid, 256>>>(feat, W);

    dim3 sgrid(N_DIM / 256, NVB);                  // (8, 128)
    bn_stats<<<sgrid, 256>>>(gamma, beta);

    sparsemax_fused<<<B_ROWS, 256>>>(priors, out);
}

// round 4
// speedup vs baseline: 1.5859x; 1.5859x over previous
#include <cuda_runtime.h>
#include <cuda_bf16.h>
#include <cstdint>

#define B_ROWS 32768
#define K_DIM  512
#define N_DIM  2048
#define VBS    256
#define NVB    128

// ---------------- scratch (device globals; no allocations allowed) ----------
__device__ __align__(16) float g_Y[(size_t)B_ROWS * N_DIM];
__device__ __align__(16) float g_scale[NVB * N_DIM];
__device__ __align__(16) float g_shift[NVB * N_DIM];
__device__ __align__(16) __nv_bfloat16 g_Ahi[(size_t)B_ROWS * K_DIM];
__device__ __align__(16) __nv_bfloat16 g_Alo[(size_t)B_ROWS * K_DIM];
__device__ __align__(16) __nv_bfloat16 g_Whi[(size_t)N_DIM * K_DIM];
__device__ __align__(16) __nv_bfloat16 g_Wlo[(size_t)N_DIM * K_DIM];

// ---------------- PTX helpers (base sm_103 target only — NO 'a' features) ---
__device__ __forceinline__ uint32_t smem_u32(const void* p) {
    uint32_t a;
    asm("{ .reg .u64 t; cvta.to.shared.u64 t, %1; cvt.u32.u64 %0, t; }" : "=r"(a) : "l"(p));
    return a;
}
#define CP_ASYNC16(dst, src) \
    asm volatile("cp.async.cg.shared.global [%0], [%1], 16;" :: "r"(dst), "l"(src))
#define CP_COMMIT() asm volatile("cp.async.commit_group;")
#define CP_WAIT2()  asm volatile("cp.async.wait_group 2;")
#define LDMX4(r0, r1, r2, r3, addr) \
    asm volatile("ldmatrix.sync.aligned.m8n8.x4.shared.b16 {%0,%1,%2,%3}, [%4];" \
        : "=r"(r0), "=r"(r1), "=r"(r2), "=r"(r3) : "r"(addr))
#define MMA16816(d, a, b) \
    asm volatile("mma.sync.aligned.m16n8k16.row.col.f32.bf16.bf16.f32 " \
        "{%0,%1,%2,%3}, {%4,%5,%6,%7}, {%8,%9}, {%0,%1,%2,%3};" \
        : "+f"((d)[0]), "+f"((d)[1]), "+f"((d)[2]), "+f"((d)[3]) \
        : "r"((a)[0]), "r"((a)[1]), "r"((a)[2]), "r"((a)[3]), "r"((b)[0]), "r"((b)[1]))

// ---------------- kernel 0: fp32 -> bf16 hi/lo split -------------------------
__global__ __launch_bounds__(256)
void split_bf16(const float4* __restrict__ src, uint2* __restrict__ hi, uint2* __restrict__ lo, int n4) {
    int i = blockIdx.x * 256 + threadIdx.x;
    if (i >= n4) return;
    float4 v = src[i];
    __nv_bfloat16 h0 = __float2bfloat16_rn(v.x), h1 = __float2bfloat16_rn(v.y);
    __nv_bfloat16 h2 = __float2bfloat16_rn(v.z), h3 = __float2bfloat16_rn(v.w);
    __nv_bfloat16 l0 = __float2bfloat16_rn(v.x - __bfloat162float(h0));
    __nv_bfloat16 l1 = __float2bfloat16_rn(v.y - __bfloat162float(h1));
    __nv_bfloat16 l2 = __float2bfloat16_rn(v.z - __bfloat162float(h2));
    __nv_bfloat16 l3 = __float2bfloat16_rn(v.w - __bfloat162float(h3));
    hi[i] = make_uint2((uint32_t)__bfloat16_as_ushort(h0) | ((uint32_t)__bfloat16_as_ushort(h1) << 16),
                       (uint32_t)__bfloat16_as_ushort(h2) | ((uint32_t)__bfloat16_as_ushort(h3) << 16));
    lo[i] = make_uint2((uint32_t)__bfloat16_as_ushort(l0) | ((uint32_t)__bfloat16_as_ushort(l1) << 16),
                       (uint32_t)__bfloat16_as_ushort(l2) | ((uint32_t)__bfloat16_as_ushort(l3) << 16));
}

// ---------------- kernel 1: HMMA GEMM  Y = A @ W^T (3-term split bf16) ------
// CTA 128x128, 8 warps (2M x 4N), warp tile 64x32, k-step 32, 48 iters (K'=1536).
// Smem rows padded to 80B: pitch = 5 x 16B chunks, 5 odd => ldmatrix row
// addresses cover all 8 chunk offsets mod 128B -> conflict-free, no swizzle.
#define STAGES      4
#define PITCH       80
#define A_STAGE     (128 * PITCH)        // 10240 B
#define STAGE_BYTES (2 * A_STAGE)        // 20480 B
#define GEMM_SMEM   (STAGES * STAGE_BYTES)   // 81920 B
#define NITER       48

__global__ __launch_bounds__(256, 1)
void gemm_mma() {
    extern __shared__ char sm[];
    const int tid  = threadIdx.x;
    const int lane = tid & 31;
    const int warp = tid >> 5;
    const int bm = blockIdx.y * 128;
    const int bn = blockIdx.x * 128;
    const int wm = (warp >> 2) * 64;     // warp m-offset in tile
    const int wn = (warp & 3) * 32;      // warp n-offset in tile

    const uint32_t sbase = smem_u32(sm);

    float acc[4][4][4];
    #pragma unroll
    for (int i = 0; i < 4; i++)
        #pragma unroll
        for (int j = 0; j < 4; j++)
            #pragma unroll
            for (int r = 0; r < 4; r++) acc[i][j][r] = 0.f;

    // per-lane ldmatrix base offsets (within a stage)
    const uint32_t a_off = (uint32_t)(wm + (lane & 15)) * PITCH + ((lane >> 4) & 1) * 16;
    const uint32_t b_off = A_STAGE +
        (uint32_t)(wn + (lane & 7) + ((lane >> 4) & 1) * 8) * PITCH + ((lane >> 3) & 1) * 16;

    // loader: iter -> (pass, kk); 256 threads load 2 A-chunks + 2 W-chunks each
    auto load_stage = [&](int iter, int stage) {
        const int pass = iter >> 4;
        const int kk   = (iter & 15) * 32;
        const __nv_bfloat16* Ap = (pass == 2) ? g_Alo : g_Ahi;
        const __nv_bfloat16* Wp = (pass == 1) ? g_Wlo : g_Whi;
        const uint32_t as = sbase + stage * STAGE_BYTES;
        const uint32_t ws = as + A_STAGE;
        #pragma unroll
        for (int j = 0; j < 2; j++) {
            const int i   = tid + j * 256;
            const int row = i >> 2;
            const int c   = i & 3;
            CP_ASYNC16(as + row * PITCH + c * 16, Ap + (size_t)(bm + row) * K_DIM + kk + c * 8);
            CP_ASYNC16(ws + row * PITCH + c * 16, Wp + (size_t)(bn + row) * K_DIM + kk + c * 8);
        }
        CP_COMMIT();
    };

    load_stage(0, 0);
    load_stage(1, 1);
    load_stage(2, 2);

    for (int iter = 0; iter < NITER; iter++) {
        const int stage = iter & 3;
        CP_WAIT2();
        __syncthreads();
        if (iter + 3 < NITER) load_stage(iter + 3, (iter + 3) & 3);
        else                  CP_COMMIT();          // empty group keeps wait-count uniform

        const uint32_t as = sbase + stage * STAGE_BYTES;
        #pragma unroll
        for (int s = 0; s < 2; s++) {               // two k16 sub-steps
            uint32_t af[4][4];
            #pragma unroll
            for (int mf = 0; mf < 4; mf++)
                LDMX4(af[mf][0], af[mf][1], af[mf][2], af[mf][3],
                      as + a_off + mf * 16 * PITCH + s * 32);
            uint32_t bf[4][2];
            #pragma unroll
            for (int p = 0; p < 2; p++) {
                uint32_t r0, r1, r2, r3;
                LDMX4(r0, r1, r2, r3, as + b_off + p * 16 * PITCH + s * 32);
                bf[2 * p][0] = r0; bf[2 * p][1] = r1;
                bf[2 * p + 1][0] = r2; bf[2 * p + 1][1] = r3;
            }
            #pragma unroll
            for (int mf = 0; mf < 4; mf++)
                #pragma unroll
                for (int nf = 0; nf < 4; nf++)
                    MMA16816(acc[mf][nf], af[mf], bf[nf]);
        }
    }

    // epilogue: fragment layout -> g_Y
    #pragma unroll
    for (int mf = 0; mf < 4; mf++) {
        const int gm = bm + wm + mf * 16 + (lane >> 2);
        #pragma unroll
        for (int nf = 0; nf < 4; nf++) {
            const int gn = bn + wn + nf * 8 + (lane & 3) * 2;
            *(float2*)(g_Y + (size_t)gm * N_DIM + gn)       = make_float2(acc[mf][nf][0], acc[mf][nf][1]);
            *(float2*)(g_Y + (size_t)(gm + 8) * N_DIM + gn) = make_float2(acc[mf][nf][2], acc[mf][nf][3]);
        }
    }
}

// ---------------- kernel 2: GhostBatchNorm stats (fold gamma/beta) ----------
__global__ __launch_bounds__(256)
void bn_stats(const float* __restrict__ gamma, const float* __restrict__ beta) {
    const int d  = blockIdx.x * 256 + threadIdx.x;
    const int vb = blockIdx.y;
    const float* p = g_Y + (size_t)vb * VBS * N_DIM + d;
    float s = 0.f, s2 = 0.f;
    #pragma unroll 8
    for (int r = 0; r < VBS; r++) {
        float v = p[(size_t)r * N_DIM];
        s += v;
        s2 = fmaf(v, v, s2);
    }
    float mean = s * (1.f / VBS);
    float var  = s2 * (1.f / VBS) - mean * mean;
    float sc   = gamma[d] * rsqrtf(var + 1e-5f);
    g_scale[vb * N_DIM + d] = sc;
    g_shift[vb * N_DIM + d] = fmaf(-mean, sc, beta[d]);
}

// ---------------- kernel 3: fused BN-apply + prior + exact sparsemax --------
__global__ __launch_bounds__(256)
void sparsemax_fused(const float* __restrict__ priors, float* __restrict__ out) {
    const int row = blockIdx.x;
    const int vb  = row >> 8;
    const int t   = threadIdx.x;
    const int c0  = t * 8;

    __shared__ float warp_s[8];
    __shared__ float warp_c[8];
    __shared__ float bcast[2];

    const float* yrow = g_Y     + (size_t)row * N_DIM;
    const float* prow = priors  + (size_t)row * N_DIM;
    const float* scr  = g_scale + (size_t)vb * N_DIM;
    const float* shr  = g_shift + (size_t)vb * N_DIM;

    float z[8];
    #pragma unroll
    for (int v = 0; v < 2; v++) {
        float4 y  = *(const float4*)(yrow + c0 + v * 4);
        float4 p  = *(const float4*)(prow + c0 + v * 4);
        float4 sc = *(const float4*)(scr  + c0 + v * 4);
        float4 sh = *(const float4*)(shr  + c0 + v * 4);
        z[v * 4 + 0] = fmaf(y.x, sc.x, sh.x) * p.x;
        z[v * 4 + 1] = fmaf(y.y, sc.y, sh.y) * p.y;
        z[v * 4 + 2] = fmaf(y.z, sc.z, sh.z) * p.z;
        z[v * 4 + 3] = fmaf(y.w, sc.w, sh.w) * p.w;
    }

    float ls = 0.f, lc = 0.f;
    #pragma unroll
    for (int i = 0; i < 8; i++) ls += z[i];
    #pragma unroll
    for (int o = 16; o; o >>= 1) ls += __shfl_down_sync(0xffffffffu, ls, o);
    if ((t & 31) == 0) warp_s[t >> 5] = ls;
    __syncthreads();
    if (t < 32) {
        float s = (t < 8) ? warp_s[t] : 0.f;
        #pragma unroll
        for (int o = 4; o; o >>= 1) s += __shfl_down_sync(0xffffffffu, s, o);
        if (t == 0) bcast[0] = s;
    }
    __syncthreads();
    float tau   = (bcast[0] - 1.f) * (1.f / (float)N_DIM);
    float kprev = (float)N_DIM;
    __syncthreads();

    for (int it = 0; it < 64; it++) {
        ls = 0.f; lc = 0.f;
        #pragma unroll
        for (int i = 0; i < 8; i++)
            if (z[i] > tau) { ls += z[i]; lc += 1.f; }
        #pragma unroll
        for (int o = 16; o; o >>= 1) {
            ls += __shfl_down_sync(0xffffffffu, ls, o);
            lc += __shfl_down_sync(0xffffffffu, lc, o);
        }
        if ((t & 31) == 0) { warp_s[t >> 5] = ls; warp_c[t >> 5] = lc; }
        __syncthreads();
        if (t < 32) {
            float s = (t < 8) ? warp_s[t] : 0.f;
            float c = (t < 8) ? warp_c[t] : 0.f;
            #pragma unroll
            for (int o = 4; o; o >>= 1) {
                s += __shfl_down_sync(0xffffffffu, s, o);
                c += __shfl_down_sync(0xffffffffu, c, o);
            }
            if (t == 0) { bcast[0] = s; bcast[1] = c; }
        }
        __syncthreads();
        float S = bcast[0];
        float C = bcast[1];
        __syncthreads();
        if (C == kprev) break;
        tau   = (S - 1.f) / C;
        kprev = C;
    }

    float o0[8];
    #pragma unroll
    for (int i = 0; i < 8; i++) o0[i] = fmaxf(z[i] - tau, 0.f);
    float* orow = out + (size_t)row * N_DIM + c0;
    *(float4*)(orow)     = make_float4(o0[0], o0[1], o0[2], o0[3]);
    *(float4*)(orow + 4) = make_float4(o0[4], o0[5], o0[6], o0[7]);
}

// ---------------- host side --------------------------------------------------
extern "C" void kernel_launch(void* const* d_in, const int* in_sizes, int n_in,
                              void* d_out, int out_size) {
    const float* priors = (const float*)d_in[0];
    const float* feat   = (const float*)d_in[1];
    const float* W      = (const float*)d_in[2];
    const float* gamma  = (const float*)d_in[3];
    const float* beta   = (const float*)d_in[4];
    float* out = (float*)d_out;

    void *pAhi, *pAlo, *pWhi, *pWlo;
    cudaGetSymbolAddress(&pAhi, g_Ahi);
    cudaGetSymbolAddress(&pAlo, g_Alo);
    cudaGetSymbolAddress(&pWhi, g_Whi);
    cudaGetSymbolAddress(&pWlo, g_Wlo);

    cudaFuncSetAttribute(gemm_mma, cudaFuncAttributeMaxDynamicSharedMemorySize, GEMM_SMEM);

    // split fp32 -> bf16 hi/lo
    split_bf16<<<(B_ROWS * K_DIM / 4 + 255) / 256, 256>>>((const float4*)feat, (uint2*)pAhi, (uint2*)pAlo, B_ROWS * K_DIM / 4);
    split_bf16<<<(N_DIM * K_DIM / 4 + 255) / 256, 256>>>((const float4*)W, (uint2*)pWhi, (uint2*)pWlo, N_DIM * K_DIM / 4);

    // tensor-core GEMM (HMMA)
    dim3 ggrid(N_DIM / 128, B_ROWS / 128);   // (16, 256)
    gemm_mma<<<ggrid, 256, GEMM_SMEM>>>();

    // BN stats + fused epilogue
    dim3 sgrid(N_DIM / 256, NVB);
    bn_stats<<<sgrid, 256>>>(gamma, beta);
    sparsemax_fused<<<B_ROWS, 256>>>(priors, out);
}